// round 15
// baseline (speedup 1.0000x reference)
#include <cuda_runtime.h>
#include <cstdint>

// Spatial correlation sampler:
// out[b, di*9+dj, i, j] = (1/C) * sum_c x[b,c,i,j] * y[b,c,i+di-4, j+dj-4]  (zero-padded)
// x,y = [16, 256, 64, 64] fp32; out = [16, 81, 64, 64] fp32.

#define BB 16
#define CH 256
#define HH 64
#define WW 64
#define TH 8            // output rows per CTA
#define CC 4            // channels per smem stage
#define NS (CH / CC)    // 64 stages
#define DI_CHUNK 3
#define YR (TH + 2)     // 10 y rows per stage
#define YW 72           // 64 + 2*4 pad
#define YF4 (CC * YR * 18)       // 720 float4 per y stage
#define CHSTR (HH * WW)          // channel stride (floats)
#define STAGESTR (CC * CHSTR)    // gmem advance per stage (floats)
#define NBUF 3

#define FMA2(acc, a, b) \
    asm("fma.rn.f32x2 %0, %1, %2, %0;" : "+l"(acc) : "l"(a), "l"(b))
#define PACK2(r, lo, hi) \
    asm("mov.b64 %0, {%1, %2};" : "=l"(r) : "r"(__float_as_uint(lo)), "r"(__float_as_uint(hi)))
#define UNPK2(lo, hi, r) \
    asm("mov.b64 {%0, %1}, %2;" : "=f"(lo), "=f"(hi) : "l"(r))

__device__ __forceinline__ void cpa16(uint32_t saddr, const void* gptr, int src_bytes) {
    asm volatile("cp.async.cg.shared.global [%0], [%1], 16, %2;\n"
                 :: "r"(saddr), "l"(gptr), "r"(src_bytes));
}

__global__ __launch_bounds__(128, 3)
void corr_kernel(const float* __restrict__ x,
                 const float* __restrict__ y,
                 float* __restrict__ out)
{
    __shared__ float ys[NBUF][CC][YR][YW];   // 3 * 11.25 KB = 33.75 KB

    const int tid = threadIdx.x;       // 128 threads
    const int jg  = tid & 15;
    const int ti  = tid >> 4;
    const int j0  = jg * 4;            // 4 pixels per thread
    const int i0  = blockIdx.x * TH;
    const int g   = blockIdx.y * DI_CHUNK;
    const int b   = blockIdx.z;        // batch slowest -> L2 locality across passes

    const float* xb = x + (size_t)b * CH * CHSTR;
    const float* yb = y + (size_t)b * CH * CHSTR;

    const uint32_t ys_s  = (uint32_t)__cvta_generic_to_shared(&ys[0][0][0][0]);
    const uint32_t ys_sz = sizeof(float) * CC * YR * YW;

    // ---- y loader addresses (hoisted): 720 float4/stage -> up to 6 per thread
    const float* gyp[6]; uint32_t sy[6]; int ybytes[6]; bool yvalid[6];
#pragma unroll
    for (int e = 0; e < 6; e++) {
        int f = tid + e * 128;
        yvalid[e] = (f < YF4);
        int fc = yvalid[e] ? f : 0;
        int c   = fc / (YR * 18);
        int rem = fc % (YR * 18);
        int r   = rem / 18;
        int q   = rem % 18;
        int gy  = i0 + g - 4 + r;
        bool ok = (gy >= 0) && (gy < HH) && (q > 0) && (q < 17);
        int gyc = gy < 0 ? 0 : (gy > HH - 1 ? HH - 1 : gy);
        int gq  = ok ? (q * 4 - 4) : 0;
        gyp[e]    = yb + c * CHSTR + gyc * WW + gq;
        sy[e]     = ys_s + (uint32_t)(((c * YR + r) * YW) + q * 4) * 4u;
        ybytes[e] = ok ? 16 : 0;
    }

    // ---- x register stream: this thread's own float4 per channel, prefetch depth 2
    const float* xq = xb + (i0 + ti) * WW + j0;     // c = 0 address
    float4 xa0 = *(const float4*)xq;                // c = 0
    float4 xa1 = *(const float4*)(xq + CHSTR);      // c = 1
    const float* xg = xq + 2 * CHSTR;               // next to fetch: c = 2

    // f32x2 accumulators
    unsigned long long acc2[DI_CHUNK][9][2];
#pragma unroll
    for (int a = 0; a < DI_CHUNK; a++)
#pragma unroll
        for (int d = 0; d < 9; d++) { acc2[a][d][0] = 0ull; acc2[a][d][1] = 0ull; }

    // ---- issue one y stage's cp.asyncs (call strictly sequentially: advances ptrs)
    auto issue_stage = [&](int sel) {
        uint32_t yo = (uint32_t)sel * ys_sz;
#pragma unroll
        for (int e = 0; e < 6; e++) {
            if (yvalid[e]) {
                cpa16(sy[e] + yo, gyp[e], ybytes[e]);
                gyp[e] += STAGESTR;
            }
        }
        asm volatile("cp.async.commit_group;\n");
    };

    issue_stage(0);
    issue_stage(1);

    for (int t = 0; t < NS; t++) {
        const int sel = t % NBUF;
        // ensure group t complete; keep group t+1 in flight
        if (t < NS - 1) asm volatile("cp.async.wait_group 1;\n");
        else            asm volatile("cp.async.wait_group 0;\n");
        __syncthreads();                          // single barrier per stage
        if (t + 2 < NS) issue_stage((t + 2) % NBUF);

        // ---- compute on buffer `sel`; x streamed from registers
#pragma unroll
        for (int c = 0; c < CC; c++) {
            float4 xv = (c & 1) ? xa1 : xa0;
            unsigned long long xlo, xhi;
            PACK2(xlo, xv.x, xv.y);
            PACK2(xhi, xv.z, xv.w);
#pragma unroll
            for (int a = 0; a < DI_CHUNK; a++) {
                float4 t0 = *(const float4*)&ys[sel][c][ti + a][j0 + 0];
                float4 t1 = *(const float4*)&ys[sel][c][ti + a][j0 + 4];
                float4 t2 = *(const float4*)&ys[sel][c][ti + a][j0 + 8];
                float wv[12] = { t0.x, t0.y, t0.z, t0.w,
                                 t1.x, t1.y, t1.z, t1.w,
                                 t2.x, t2.y, t2.z, t2.w };
                unsigned long long wp[11];
#pragma unroll
                for (int k = 0; k < 11; k++) PACK2(wp[k], wv[k], wv[k + 1]);
#pragma unroll
                for (int d = 0; d < 9; d++) {
                    FMA2(acc2[a][d][0], xlo, wp[d]);
                    FMA2(acc2[a][d][1], xhi, wp[d + 2]);
                }
            }
            // prefetch x for channel ci+2 into the slot just consumed
            const int ci = t * CC + c;
            if (ci + 2 < CH) {
                float4 nv = *(const float4*)xg;
                if (c & 1) xa1 = nv; else xa0 = nv;
                xg += CHSTR;
            }
        }
        // no trailing barrier: next iteration's top barrier protects buffer reuse
    }

    // ---- epilogue: scale by 1/C, coalesced float4 stores
    const float s = 1.0f / (float)CH;
#pragma unroll
    for (int a = 0; a < DI_CHUNK; a++) {
#pragma unroll
        for (int d = 0; d < 9; d++) {
            int dd = (g + a) * 9 + d;
            float v0, v1, v2, v3;
            UNPK2(v0, v1, acc2[a][d][0]);
            UNPK2(v2, v3, acc2[a][d][1]);
            float4 v = make_float4(v0 * s, v1 * s, v2 * s, v3 * s);
            *(float4*)&out[(((size_t)b * 81 + dd) * HH + (i0 + ti)) * WW + j0] = v;
        }
    }
}

extern "C" void kernel_launch(void* const* d_in, const int* in_sizes, int n_in,
                              void* d_out, int out_size)
{
    const float* x = (const float*)d_in[0];
    const float* y = (const float*)d_in[1];
    float* out = (float*)d_out;

    dim3 grid(HH / TH, 9 / DI_CHUNK, BB);   // (8, 3, 16) = 384 CTAs, single wave @ 3 CTA/SM
    dim3 block(128);
    corr_kernel<<<grid, block>>>(x, y, out);
}